// round 2
// baseline (speedup 1.0000x reference)
#include <cuda_runtime.h>
#include <cstdint>

#define NPTS   32768
#define MTOT   131072      // B*N = 4*32768
#define KNB    16
#define CIN    64
#define CDEL   32
#define CALL   96          // CDEL + CIN
#define COUT   128
#define KC     1536        // KNB*CALL  (conv GEMM reduction dim)

// ---- scratch (static device globals; no runtime allocation) ----
__device__ float d_H[(size_t)MTOT * 256];      // hidden layer of X-MLP
__device__ float d_X[(size_t)MTOT * 256];      // per-point KxK transform (flat k*16+j)
__device__ float d_fall[(size_t)MTOT * KC];    // transformed f_all, [m][k*96+c]

// =====================================================================
// Kernel H: per 64-point tile. Gather coords -> prel (64x48) in smem,
// then H = relu(prel @ Wx1 + bx1)  (64x256, K=48, Wx1 streamed 16 rows
// at a time).  Static smem: 12KB + 16KB + 1KB = 29KB.
// =====================================================================
__global__ __launch_bounds__(256) void kH(
    const float* __restrict__ coords, const int* __restrict__ knn,
    const float* __restrict__ Wx1, const float* __restrict__ bx1)
{
    __shared__ float s_prel[64 * 48];
    __shared__ float s_w[16 * 256];
    __shared__ float s_b[256];

    const int t  = threadIdx.x;
    const int m0 = blockIdx.x * 64;

    // ---- relative coordinates (gather) ----
    for (int task = t; task < 64 * 16; task += 256) {
        int i = task >> 4, k = task & 15;
        int m = m0 + i;
        int b = m >> 15;
        const float* cc = coords + (size_t)m * 3;
        float cx = cc[0], cy = cc[1], cz = cc[2];
        int idx = knn[(size_t)m * KNB + k];
        const float* nc = coords + ((size_t)(b << 15) + idx) * 3;
        s_prel[i*48 + k*3 + 0] = nc[0] - cx;
        s_prel[i*48 + k*3 + 1] = nc[1] - cy;
        s_prel[i*48 + k*3 + 2] = nc[2] - cz;
    }
    s_b[t] = bx1[t];

    const int tr = t >> 5;     // warp id 0..7 -> rows tr*8 + r
    const int tc = t & 31;     // lane -> cols tc + 32*c

    float acc[8][8];
    __syncthreads();
    #pragma unroll
    for (int r = 0; r < 8; r++)
        #pragma unroll
        for (int c = 0; c < 8; c++) acc[r][c] = s_b[tc + 32*c];

    for (int kk = 0; kk < 48; kk += 16) {
        __syncthreads();
        #pragma unroll
        for (int i = 0; i < 4; i++) {
            int j = t + i * 256;                       // 1024 float4
            ((float4*)s_w)[j] = ((const float4*)(Wx1 + (size_t)kk * 256))[j];
        }
        __syncthreads();
        #pragma unroll
        for (int q = 0; q < 16; q++) {
            float a[8];
            #pragma unroll
            for (int r = 0; r < 8; r++) a[r] = s_prel[(tr*8 + r)*48 + kk + q];
            #pragma unroll
            for (int c = 0; c < 8; c++) {
                float wv = s_w[q*256 + tc + 32*c];
                #pragma unroll
                for (int r = 0; r < 8; r++) acc[r][c] = fmaf(a[r], wv, acc[r][c]);
            }
        }
    }
    #pragma unroll
    for (int r = 0; r < 8; r++)
        #pragma unroll
        for (int c = 0; c < 8; c++)
            d_H[(size_t)(m0 + tr*8 + r)*256 + tc + 32*c] = fmaxf(acc[r][c], 0.0f);
}

// =====================================================================
// Kernel X: X = H @ Wx2  (M x 256, K = 256).  Standard 128x128 tile,
// BK=16, 256 threads, 8x8 register micro-tiles.  Smem 16KB.
// =====================================================================
__global__ __launch_bounds__(256) void kX(const float* __restrict__ Wx2)
{
    __shared__ float s_a[128 * 16];   // [row][q]
    __shared__ float s_w[16 * 128];   // [q][col]

    const int t  = threadIdx.x;
    const int m0 = blockIdx.x * 128;
    const int n0 = blockIdx.y * 128;
    const int tr = t >> 4;            // rows tr*8 + r
    const int tc = t & 15;            // cols tc + 16*c

    float acc[8][8];
    #pragma unroll
    for (int r = 0; r < 8; r++)
        #pragma unroll
        for (int c = 0; c < 8; c++) acc[r][c] = 0.0f;

    for (int kk = 0; kk < 256; kk += 16) {
        __syncthreads();
        #pragma unroll
        for (int i = 0; i < 2; i++) {
            int task = t + i*256;
            int row = task >> 2, f4 = task & 3;
            ((float4*)s_a)[task] =
                *(const float4*)(d_H + (size_t)(m0 + row)*256 + kk + 4*f4);
        }
        #pragma unroll
        for (int i = 0; i < 2; i++) {
            int task = t + i*256;
            int q = task >> 5, c4 = task & 31;
            ((float4*)s_w)[task] =
                *(const float4*)(Wx2 + (size_t)(kk + q)*256 + n0 + 4*c4);
        }
        __syncthreads();

        #pragma unroll
        for (int q = 0; q < 16; q++) {
            float a[8];
            #pragma unroll
            for (int r = 0; r < 8; r++) a[r] = s_a[(tr*8 + r)*16 + q];
            #pragma unroll
            for (int c = 0; c < 8; c++) {
                float wv = s_w[q*128 + tc + 16*c];
                #pragma unroll
                for (int r = 0; r < 8; r++) acc[r][c] = fmaf(a[r], wv, acc[r][c]);
            }
        }
    }
    #pragma unroll
    for (int r = 0; r < 8; r++)
        #pragma unroll
        for (int c = 0; c < 8; c++)
            d_X[(size_t)(m0 + tr*8 + r)*256 + n0 + tc + 16*c] = acc[r][c];
}

// =====================================================================
// Kernel B1: one warp per point. Gather nbr feats, compute f_delta,
// assemble g (16x96) in smem, apply X-transform, write f_all (1536/pt).
// 128 threads = 4 points/CTA.  Static smem 28KB.
// =====================================================================
__global__ __launch_bounds__(128) void kB1(
    const float* __restrict__ coords, const float* __restrict__ feats,
    const int* __restrict__ knn,
    const float* __restrict__ Wd, const float* __restrict__ bd)
{
    __shared__ float s_g[4][KC];
    __shared__ float s_x[4][256];

    const int w = threadIdx.x >> 5;
    const int l = threadIdx.x & 31;
    const size_t m = (size_t)blockIdx.x * 4 + w;
    const int   b = (int)(m >> 15);
    const size_t base = (size_t)b << 15;

    for (int j = l; j < 256; j += 32) s_x[w][j] = d_X[m*256 + j];

    const float* cc = coords + m*3;
    float cx = cc[0], cy = cc[1], cz = cc[2];
    float wd0 = Wd[l], wd1 = Wd[32 + l], wd2 = Wd[64 + l], bdl = bd[l];

    #pragma unroll
    for (int k = 0; k < KNB; k++) {
        int idx = knn[m*KNB + k];
        const float* nf = feats + (base + idx) * CIN;   // channels [32,96)
        float2 v = ((const float2*)nf)[l];
        s_g[w][k*CALL + CDEL + 2*l    ] = v.x;
        s_g[w][k*CALL + CDEL + 2*l + 1] = v.y;
        const float* nc = coords + (base + idx)*3;      // f_delta -> [0,32)
        float px = nc[0]-cx, py = nc[1]-cy, pz = nc[2]-cz;
        float fd = fmaf(pz, wd2, fmaf(py, wd1, fmaf(px, wd0, bdl)));
        s_g[w][k*CALL + l] = fmaxf(fd, 0.0f);
    }
    __syncwarp();

    // f_all[k,c] = sum_j X[k,j] * g[j,c];  lane l covers c in {l,l+32,l+64}
    float o0[16], o1[16], o2[16];
    #pragma unroll
    for (int k = 0; k < 16; k++) { o0[k] = 0.f; o1[k] = 0.f; o2[k] = 0.f; }

    #pragma unroll
    for (int j = 0; j < 16; j++) {
        float g0 = s_g[w][j*CALL + l];
        float g1 = s_g[w][j*CALL + 32 + l];
        float g2 = s_g[w][j*CALL + 64 + l];
        #pragma unroll
        for (int k = 0; k < 16; k++) {
            float xv = s_x[w][k*16 + j];
            o0[k] = fmaf(xv, g0, o0[k]);
            o1[k] = fmaf(xv, g1, o1[k]);
            o2[k] = fmaf(xv, g2, o2[k]);
        }
    }
    float* dst = d_fall + m*KC;
    #pragma unroll
    for (int k = 0; k < 16; k++) {
        dst[k*CALL + l]      = o0[k];
        dst[k*CALL + 32 + l] = o1[k];
        dst[k*CALL + 64 + l] = o2[k];
    }
}

// =====================================================================
// Kernel B2: out[M,128] = f_all[M,1536] @ Wconv[1536,128] + bconv.
// 128x128 tile, BK=16, 256 threads, 8x8 register micro-tiles.
// =====================================================================
__global__ __launch_bounds__(256) void kB2(
    const float* __restrict__ Wconv, const float* __restrict__ bconv,
    float* __restrict__ out)
{
    __shared__ float s_a[128*16];   // [row][q]
    __shared__ float s_w[16*128];   // [q][col]

    const int t  = threadIdx.x;
    const int m0 = blockIdx.x * 128;
    const int tr = t >> 4;
    const int tc = t & 15;

    float acc[8][8];
    #pragma unroll
    for (int r = 0; r < 8; r++)
        #pragma unroll
        for (int c = 0; c < 8; c++) acc[r][c] = 0.0f;

    const float* Abase = d_fall + (size_t)m0 * KC;

    for (int kk = 0; kk < KC; kk += 16) {
        __syncthreads();
        #pragma unroll
        for (int i = 0; i < 2; i++) {
            int task = t + i*256;
            int row = task >> 2, f4 = task & 3;
            ((float4*)s_a)[task] =
                *(const float4*)(Abase + (size_t)row*KC + kk + 4*f4);
        }
        #pragma unroll
        for (int i = 0; i < 2; i++) {
            int task = t + i*256;
            int q = task >> 5, c4 = task & 31;
            ((float4*)s_w)[task] =
                *(const float4*)(Wconv + (size_t)(kk + q)*COUT + 4*c4);
        }
        __syncthreads();

        #pragma unroll
        for (int q = 0; q < 16; q++) {
            float a[8];
            #pragma unroll
            for (int r = 0; r < 8; r++) a[r] = s_a[(tr*8 + r)*16 + q];
            #pragma unroll
            for (int c = 0; c < 8; c++) {
                float wv = s_w[q*128 + tc + 16*c];
                #pragma unroll
                for (int r = 0; r < 8; r++) acc[r][c] = fmaf(a[r], wv, acc[r][c]);
            }
        }
    }

    float bv[8];
    #pragma unroll
    for (int c = 0; c < 8; c++) bv[c] = bconv[tc + 16*c];
    #pragma unroll
    for (int r = 0; r < 8; r++)
        #pragma unroll
        for (int c = 0; c < 8; c++)
            out[(size_t)(m0 + tr*8 + r)*COUT + tc + 16*c] = acc[r][c] + bv[c];
}

// =====================================================================
extern "C" void kernel_launch(void* const* d_in, const int* in_sizes, int n_in,
                              void* d_out, int out_size)
{
    const float* coords = (const float*)d_in[0];
    const float* feats  = (const float*)d_in[1];
    const int*   knn    = (const int*)  d_in[2];
    const float* Wd     = (const float*)d_in[3];
    const float* bd     = (const float*)d_in[4];
    const float* Wx1    = (const float*)d_in[5];
    const float* bx1    = (const float*)d_in[6];
    const float* Wx2    = (const float*)d_in[7];
    const float* Wconv  = (const float*)d_in[8];
    const float* bconv  = (const float*)d_in[9];
    float* out = (float*)d_out;

    kH <<< MTOT/64,  256 >>>(coords, knn, Wx1, bx1);
    kX <<< dim3(MTOT/128, 2), 256 >>>(Wx2);
    kB1<<< MTOT/4,   128 >>>(coords, feats, knn, Wd, bd);
    kB2<<< MTOT/128, 256 >>>(Wconv, bconv, out);
}

// round 5
// speedup vs baseline: 1.9197x; 1.9197x over previous
#include <cuda_runtime.h>
#include <cuda_bf16.h>
#include <cstdint>

#define NPTS   32768
#define MTOT   131072      // B*N
#define KNB    16
#define CIN    64
#define CDEL   32
#define CALL   96
#define COUT   128
#define KC     1536        // conv GEMM reduction dim

// ---- scratch (static device globals) ----
__device__ __align__(256) __nv_bfloat16 d_H_hi[(size_t)MTOT * 256];
__device__ __align__(256) __nv_bfloat16 d_H_lo[(size_t)MTOT * 256];
__device__ __align__(256) float         d_X   [(size_t)MTOT * 256];
__device__ __align__(256) __nv_bfloat16 d_f_hi[(size_t)MTOT * KC];
__device__ __align__(256) __nv_bfloat16 d_f_lo[(size_t)MTOT * KC];
// split + transposed weights (B operands, [n][k] K-major)
__device__ __align__(256) __nv_bfloat16 d_Wx2t_hi[256 * 256];
__device__ __align__(256) __nv_bfloat16 d_Wx2t_lo[256 * 256];
__device__ __align__(256) __nv_bfloat16 d_Wc_hi[128 * KC];
__device__ __align__(256) __nv_bfloat16 d_Wc_lo[128 * KC];

// =====================================================================
// helpers
// =====================================================================
__device__ __forceinline__ uint32_t smem_to_u32(const void* p) {
    uint32_t a;
    asm("{ .reg .u64 t; cvta.to.shared.u64 t, %1; cvt.u32.u64 %0, t; }"
        : "=r"(a) : "l"(p));
    return a;
}
#define SW128(o) ((o) ^ (((o) >> 3) & 0x70))

#define CP_ASYNC16(dst, src) \
    asm volatile("cp.async.cg.shared.global [%0], [%1], 16;" \
                 :: "r"(dst), "l"(src) : "memory")
#define CP_COMMIT() asm volatile("cp.async.commit_group;" ::: "memory")
#define CP_WAIT(n)  asm volatile("cp.async.wait_group %0;" :: "n"(n) : "memory")

#define LDSM_X4(r0, r1, r2, r3, addr) \
    asm volatile("ldmatrix.sync.aligned.m8n8.x4.shared.b16 {%0,%1,%2,%3}, [%4];" \
                 : "=r"(r0), "=r"(r1), "=r"(r2), "=r"(r3) : "r"(addr))

__device__ __forceinline__ void mma_bf16(float* c, const uint32_t* a,
                                         uint32_t b0, uint32_t b1) {
    asm volatile(
        "mma.sync.aligned.m16n8k16.row.col.f32.bf16.bf16.f32 "
        "{%0,%1,%2,%3}, {%4,%5,%6,%7}, {%8,%9}, {%0,%1,%2,%3};"
        : "+f"(c[0]), "+f"(c[1]), "+f"(c[2]), "+f"(c[3])
        : "r"(a[0]), "r"(a[1]), "r"(a[2]), "r"(a[3]), "r"(b0), "r"(b1));
}
__device__ __forceinline__ void split32(float v, __nv_bfloat16& h, __nv_bfloat16& l) {
    h = __float2bfloat16(v);
    l = __float2bfloat16(v - __bfloat162float(h));
}

// =====================================================================
// kPrep: split + transpose weights into K-major bf16 hi/lo B operands.
// =====================================================================
__global__ __launch_bounds__(256) void kPrep(
    const float* __restrict__ Wconv, const float* __restrict__ Wx2)
{
    int i = blockIdx.x * 256 + threadIdx.x;
    if (i < KC * COUT) {                       // Wconv[k][n] -> Wc[n][k]
        int k = i >> 7, n = i & 127;
        __nv_bfloat16 h, l; split32(Wconv[i], h, l);
        d_Wc_hi[(size_t)n * KC + k] = h;
        d_Wc_lo[(size_t)n * KC + k] = l;
    } else if (i < KC * COUT + 256 * 256) {    // Wx2[k][n] -> Wx2t[n][k]
        int j = i - KC * COUT;
        int k = j >> 8, n = j & 255;
        __nv_bfloat16 h, l; split32(Wx2[j], h, l);
        d_Wx2t_hi[n * 256 + k] = h;
        d_Wx2t_lo[n * 256 + k] = l;
    }
}

// =====================================================================
// kH: gather coords -> prel (64x48), H = relu(prel@Wx1+bx1), write hi/lo.
// =====================================================================
__global__ __launch_bounds__(256) void kH(
    const float* __restrict__ coords, const int* __restrict__ knn,
    const float* __restrict__ Wx1, const float* __restrict__ bx1)
{
    __shared__ float s_prel[64 * 48];
    __shared__ float s_w[16 * 256];
    __shared__ float s_b[256];

    const int t  = threadIdx.x;
    const int m0 = blockIdx.x * 64;

    for (int task = t; task < 64 * 16; task += 256) {
        int i = task >> 4, k = task & 15;
        int m = m0 + i;
        int b = m >> 15;
        const float* cc = coords + (size_t)m * 3;
        float cx = cc[0], cy = cc[1], cz = cc[2];
        int idx = knn[(size_t)m * KNB + k];
        const float* nc = coords + ((size_t)(b << 15) + idx) * 3;
        s_prel[i*48 + k*3 + 0] = nc[0] - cx;
        s_prel[i*48 + k*3 + 1] = nc[1] - cy;
        s_prel[i*48 + k*3 + 2] = nc[2] - cz;
    }
    s_b[t] = bx1[t];

    const int tr = t >> 5, tc = t & 31;
    float acc[8][8];
    __syncthreads();
    #pragma unroll
    for (int r = 0; r < 8; r++)
        #pragma unroll
        for (int c = 0; c < 8; c++) acc[r][c] = s_b[tc + 32*c];

    for (int kk = 0; kk < 48; kk += 16) {
        __syncthreads();
        #pragma unroll
        for (int i = 0; i < 4; i++) {
            int j = t + i * 256;
            ((float4*)s_w)[j] = ((const float4*)(Wx1 + (size_t)kk * 256))[j];
        }
        __syncthreads();
        #pragma unroll
        for (int q = 0; q < 16; q++) {
            float a[8];
            #pragma unroll
            for (int r = 0; r < 8; r++) a[r] = s_prel[(tr*8 + r)*48 + kk + q];
            #pragma unroll
            for (int c = 0; c < 8; c++) {
                float wv = s_w[q*256 + tc + 32*c];
                #pragma unroll
                for (int r = 0; r < 8; r++) acc[r][c] = fmaf(a[r], wv, acc[r][c]);
            }
        }
    }
    #pragma unroll
    for (int r = 0; r < 8; r++)
        #pragma unroll
        for (int c = 0; c < 8; c++) {
            float v = fmaxf(acc[r][c], 0.0f);
            __nv_bfloat16 h, l; split32(v, h, l);
            size_t o = (size_t)(m0 + tr*8 + r)*256 + tc + 32*c;
            d_H_hi[o] = h; d_H_lo[o] = l;
        }
}

// =====================================================================
// kGemm: D[M,*] = A[M,KTOT] @ B[n][k]^T via split-bf16 mma.sync (3 MMAs).
// CTA tile 128m x 128n, BK=64 (128B rows, SW128), cp.async double buffer.
// 8 warps: wm = w&3 (32 rows), wn = w>>2 (64 cols).
// =====================================================================
template<int KTOT, int NOUTLD, bool BIAS>
__global__ __launch_bounds__(256) void kGemm(
    const __nv_bfloat16* __restrict__ Ahi, const __nv_bfloat16* __restrict__ Alo,
    const __nv_bfloat16* __restrict__ Bhi, const __nv_bfloat16* __restrict__ Blo,
    const float* __restrict__ bias, float* __restrict__ out)
{
    extern __shared__ char smem[];
    const uint32_t sb = smem_to_u32(smem);
    const int t = threadIdx.x, w = t >> 5, l = t & 31;
    const int m0 = blockIdx.x * 128;
    const int n0 = blockIdx.y * 128;
    const int wm = w & 3, wn = w >> 2;

    const __nv_bfloat16* Bh = Bhi + (size_t)n0 * KTOT;
    const __nv_bfloat16* Bl = Blo + (size_t)n0 * KTOT;

    constexpr uint32_t ST = 65536;   // stage stride: AH 0 | AL 16K | BH 32K | BL 48K
    constexpr int NIT = KTOT / 64;

    float acc[2][8][4];
    #pragma unroll
    for (int mf = 0; mf < 2; mf++)
        #pragma unroll
        for (int nf = 0; nf < 8; nf++)
            #pragma unroll
            for (int r = 0; r < 4; r++) acc[mf][nf][r] = 0.0f;

    // ---- prefetch stage 0 ----
    {
        uint32_t base = sb;
        #pragma unroll
        for (int i0 = 0; i0 < 4; i0++) {
            int i = t + i0 * 256;
            int row = i >> 3, ch = i & 7;
            uint32_t so = SW128((uint32_t)(row*128 + ch*16));
            size_t goA = (size_t)(m0 + row) * KTOT + ch*8;
            size_t goB = (size_t)row * KTOT + ch*8;
            CP_ASYNC16(base + so,         Ahi + goA);
            CP_ASYNC16(base + 16384 + so, Alo + goA);
            CP_ASYNC16(base + 32768 + so, Bh  + goB);
            CP_ASYNC16(base + 49152 + so, Bl  + goB);
        }
        CP_COMMIT();
    }

    for (int it = 0; it < NIT; it++) {
        if (it + 1 < NIT) {
            uint32_t base = sb + ((it + 1) & 1) * ST;
            size_t kk = (size_t)(it + 1) * 64;
            #pragma unroll
            for (int i0 = 0; i0 < 4; i0++) {
                int i = t + i0 * 256;
                int row = i >> 3, ch = i & 7;
                uint32_t so = SW128((uint32_t)(row*128 + ch*16));
                size_t goA = (size_t)(m0 + row) * KTOT + kk + ch*8;
                size_t goB = (size_t)row * KTOT + kk + ch*8;
                CP_ASYNC16(base + so,         Ahi + goA);
                CP_ASYNC16(base + 16384 + so, Alo + goA);
                CP_ASYNC16(base + 32768 + so, Bh  + goB);
                CP_ASYNC16(base + 49152 + so, Bl  + goB);
            }
            CP_COMMIT();
            CP_WAIT(1);
        } else {
            CP_WAIT(0);
        }
        __syncthreads();

        const uint32_t ab = sb + (it & 1) * ST;
        #pragma unroll
        for (int s = 0; s < 4; s++) {
            // A fragments (hi, lo): rows wm*32 + mf*16 + (l%16), k16 step s
            uint32_t ah[2][4], al[2][4];
            #pragma unroll
            for (int mf = 0; mf < 2; mf++) {
                int row = wm*32 + mf*16 + (l & 15);
                uint32_t off = (uint32_t)(row*128 + s*32 + ((l >> 4) << 4));
                uint32_t sw = SW128(off);
                LDSM_X4(ah[mf][0], ah[mf][1], ah[mf][2], ah[mf][3], ab + sw);
                LDSM_X4(al[mf][0], al[mf][1], al[mf][2], al[mf][3], ab + 16384 + sw);
            }
            // B fragments: x4 covers 16 n (two n-frags)
            uint32_t bhf[4][4], blf[4][4];
            #pragma unroll
            for (int nq = 0; nq < 4; nq++) {
                int n = wn*64 + nq*16 + (l & 7) + ((l >> 4) << 3);
                uint32_t off = (uint32_t)(n*128 + s*32 + (((l >> 3) & 1) << 4));
                uint32_t sw = SW128(off);
                LDSM_X4(bhf[nq][0], bhf[nq][1], bhf[nq][2], bhf[nq][3], ab + 32768 + sw);
                LDSM_X4(blf[nq][0], blf[nq][1], blf[nq][2], blf[nq][3], ab + 49152 + sw);
            }
            #pragma unroll
            for (int mf = 0; mf < 2; mf++)
                #pragma unroll
                for (int nq = 0; nq < 4; nq++)
                    #pragma unroll
                    for (int h = 0; h < 2; h++) {
                        float* c = acc[mf][nq*2 + h];
                        mma_bf16(c, ah[mf], bhf[nq][h*2], bhf[nq][h*2+1]);
                        mma_bf16(c, ah[mf], blf[nq][h*2], blf[nq][h*2+1]);
                        mma_bf16(c, al[mf], bhf[nq][h*2], bhf[nq][h*2+1]);
                    }
        }
        __syncthreads();
    }

    // ---- epilogue ----
    #pragma unroll
    for (int mf = 0; mf < 2; mf++)
        #pragma unroll
        for (int nf = 0; nf < 8; nf++) {
            int row = wm*32 + mf*16 + (l >> 2);
            int col = n0 + wn*64 + nf*8 + (l & 3)*2;
            float b0 = 0.f, b1 = 0.f;
            if (BIAS) { b0 = __ldg(bias + col); b1 = __ldg(bias + col + 1); }
            float* o0 = out + (size_t)(m0 + row) * NOUTLD + col;
            float* o1 = out + (size_t)(m0 + row + 8) * NOUTLD + col;
            o0[0] = acc[mf][nf][0] + b0;  o0[1] = acc[mf][nf][1] + b1;
            o1[0] = acc[mf][nf][2] + b0;  o1[1] = acc[mf][nf][3] + b1;
        }
}

// =====================================================================
// kB1: warp-per-point gather + f_delta + X-transform, write f_all hi/lo.
// =====================================================================
__global__ __launch_bounds__(128) void kB1(
    const float* __restrict__ coords, const float* __restrict__ feats,
    const int* __restrict__ knn,
    const float* __restrict__ Wd, const float* __restrict__ bd)
{
    __shared__ float s_g[4][KC];
    __shared__ float s_x[4][256];

    const int w = threadIdx.x >> 5;
    const int l = threadIdx.x & 31;
    const size_t m = (size_t)blockIdx.x * 4 + w;
    const int   b = (int)(m >> 15);
    const size_t base = (size_t)b << 15;

    for (int j = l; j < 256; j += 32) s_x[w][j] = d_X[m*256 + j];

    const float* cc = coords + m*3;
    float cx = cc[0], cy = cc[1], cz = cc[2];
    float wd0 = Wd[l], wd1 = Wd[32 + l], wd2 = Wd[64 + l], bdl = bd[l];

    #pragma unroll
    for (int k = 0; k < KNB; k++) {
        int idx = knn[m*KNB + k];
        const float* nf = feats + (base + idx) * CIN;
        float2 v = ((const float2*)nf)[l];
        s_g[w][k*CALL + CDEL + 2*l    ] = v.x;
        s_g[w][k*CALL + CDEL + 2*l + 1] = v.y;
        const float* nc = coords + (base + idx)*3;
        float px = nc[0]-cx, py = nc[1]-cy, pz = nc[2]-cz;
        float fd = fmaf(pz, wd2, fmaf(py, wd1, fmaf(px, wd0, bdl)));
        s_g[w][k*CALL + l] = fmaxf(fd, 0.0f);
    }
    __syncwarp();

    float o0[16], o1[16], o2[16];
    #pragma unroll
    for (int k = 0; k < 16; k++) { o0[k] = 0.f; o1[k] = 0.f; o2[k] = 0.f; }

    #pragma unroll
    for (int j = 0; j < 16; j++) {
        float g0 = s_g[w][j*CALL + l];
        float g1 = s_g[w][j*CALL + 32 + l];
        float g2 = s_g[w][j*CALL + 64 + l];
        #pragma unroll
        for (int k = 0; k < 16; k++) {
            float xv = s_x[w][k*16 + j];
            o0[k] = fmaf(xv, g0, o0[k]);
            o1[k] = fmaf(xv, g1, o1[k]);
            o2[k] = fmaf(xv, g2, o2[k]);
        }
    }
    __nv_bfloat16 *dh = d_f_hi + m*KC, *dl = d_f_lo + m*KC;
    #pragma unroll
    for (int k = 0; k < 16; k++) {
        __nv_bfloat16 h, lo;
        split32(o0[k], h, lo); dh[k*CALL + l]      = h; dl[k*CALL + l]      = lo;
        split32(o1[k], h, lo); dh[k*CALL + 32 + l] = h; dl[k*CALL + 32 + l] = lo;
        split32(o2[k], h, lo); dh[k*CALL + 64 + l] = h; dl[k*CALL + 64 + l] = lo;
    }
}

// =====================================================================
extern "C" void kernel_launch(void* const* d_in, const int* in_sizes, int n_in,
                              void* d_out, int out_size)
{
    const float* coords = (const float*)d_in[0];
    const float* feats  = (const float*)d_in[1];
    const int*   knn    = (const int*)  d_in[2];
    const float* Wd     = (const float*)d_in[3];
    const float* bd     = (const float*)d_in[4];
    const float* Wx1    = (const float*)d_in[5];
    const float* bx1    = (const float*)d_in[6];
    const float* Wx2    = (const float*)d_in[7];
    const float* Wconv  = (const float*)d_in[8];
    const float* bconv  = (const float*)d_in[9];
    float* out = (float*)d_out;

    const int smemG = 131072;    // 2 stages x 64KB
    cudaFuncSetAttribute(kGemm<256, 256, false>,
                         cudaFuncAttributeMaxDynamicSharedMemorySize, smemG);
    cudaFuncSetAttribute(kGemm<KC, 128, true>,
                         cudaFuncAttributeMaxDynamicSharedMemorySize, smemG);

    void *pHhi, *pHlo, *pX, *pFhi, *pFlo, *pWxh, *pWxl, *pWch, *pWcl;
    cudaGetSymbolAddress(&pHhi, d_H_hi);
    cudaGetSymbolAddress(&pHlo, d_H_lo);
    cudaGetSymbolAddress(&pX,   d_X);
    cudaGetSymbolAddress(&pFhi, d_f_hi);
    cudaGetSymbolAddress(&pFlo, d_f_lo);
    cudaGetSymbolAddress(&pWxh, d_Wx2t_hi);
    cudaGetSymbolAddress(&pWxl, d_Wx2t_lo);
    cudaGetSymbolAddress(&pWch, d_Wc_hi);
    cudaGetSymbolAddress(&pWcl, d_Wc_lo);

    kPrep<<< (KC*COUT + 256*256 + 255)/256, 256 >>>(Wconv, Wx2);
    kH   <<< MTOT/64, 256 >>>(coords, knn, Wx1, bx1);
    kGemm<256, 256, false><<< dim3(MTOT/128, 2), 256, smemG >>>(
        (const __nv_bfloat16*)pHhi, (const __nv_bfloat16*)pHlo,
        (const __nv_bfloat16*)pWxh, (const __nv_bfloat16*)pWxl,
        nullptr, (float*)pX);
    kB1  <<< MTOT/4, 128 >>>(coords, feats, knn, Wd, bd);
    kGemm<KC, 128, true><<< dim3(MTOT/128, 1), 256, smemG >>>(
        (const __nv_bfloat16*)pFhi, (const __nv_bfloat16*)pFlo,
        (const __nv_bfloat16*)pWch, (const __nv_bfloat16*)pWcl,
        bconv, out);
}